// round 12
// baseline (speedup 1.0000x reference)
#include <cuda_runtime.h>
#include <cuda_fp16.h>
#include <cstdint>

// Problem constants
#define B_DIM  32
#define S_DIM  2048
#define D_DIM  768
#define NL_DIM 512
#define NF_DIM 64

#define MTOT (B_DIM * S_DIM)      // 65536

// Batch-group pipelining
#define NGROUPS 4
#define GRP (B_DIM / NGROUPS)     // 8 batches per group

// Chunked-scan geometry
#define CH_S 128
#define NCH_S (S_DIM / CH_S)      // 16
#define CH_L 64
#define NCH_L (NL_DIM / CH_L)     // 8

// ---------------------------------------------------------------------------
// Scratch (__device__ globals; allocation-free rule)
// ---------------------------------------------------------------------------
__device__ float g_lc_tok[(size_t)B_DIM * S_DIM * D_DIM];    // ~201 MB local scans
__device__ float g_lc_line[(size_t)B_DIM * NL_DIM * D_DIM];  // ~50 MB
__device__ float g_pref_tok[(size_t)B_DIM * NCH_S * D_DIM];  // chunk prefixes
__device__ float g_pref_line[(size_t)B_DIM * NCH_L * D_DIM];
__device__ __align__(128) __half g_Ah[(size_t)MTOT * D_DIM];   // ~100 MB fp16
__device__ __align__(128) __half g_Wt[(size_t)D_DIM * D_DIM];  // W^T fp16

// ---------------------------------------------------------------------------
// PTX helpers (sm_80-portable: cp.async, ldmatrix, mma.sync f16)
// ---------------------------------------------------------------------------
__device__ __forceinline__ uint32_t smem_to_u32(const void* p) {
  uint32_t a;
  asm("{ .reg .u64 t; cvta.to.shared.u64 t, %1; cvt.u32.u64 %0, t; }"
      : "=r"(a) : "l"(p));
  return a;
}

__device__ __forceinline__ void cp16(uint32_t dst, const void* src) {
  asm volatile("cp.async.cg.shared.global [%0], [%1], 16;\n" ::"r"(dst),
               "l"(src));
}
#define CP_COMMIT() asm volatile("cp.async.commit_group;\n" ::: "memory")
#define CP_WAIT(n) asm volatile("cp.async.wait_group %0;\n" ::"n"(n) : "memory")

__device__ __forceinline__ void ldsm4(uint32_t* r, uint32_t addr) {
  asm volatile(
      "ldmatrix.sync.aligned.m8n8.x4.shared.b16 {%0,%1,%2,%3}, [%4];"
      : "=r"(r[0]), "=r"(r[1]), "=r"(r[2]), "=r"(r[3])
      : "r"(addr));
}

__device__ __forceinline__ void mma16816(float* c, const uint32_t* a,
                                         uint32_t b0, uint32_t b1) {
  asm volatile(
      "mma.sync.aligned.m16n8k16.row.col.f32.f16.f16.f32 "
      "{%0,%1,%2,%3}, {%4,%5,%6,%7}, {%8,%9}, {%0,%1,%2,%3};"
      : "+f"(c[0]), "+f"(c[1]), "+f"(c[2]), "+f"(c[3])
      : "r"(a[0]), "r"(a[1]), "r"(a[2]), "r"(a[3]), "r"(b0), "r"(b1));
}

// ---------------------------------------------------------------------------
// Kernel 0a: fp32 -> fp16 (A), per group
// ---------------------------------------------------------------------------
__global__ void convert_a_kernel(const float* __restrict__ x,
                                 __half* __restrict__ ah, int n4) {
  int i = blockIdx.x * blockDim.x + threadIdx.x;
  if (i >= n4) return;
  float4 v = ((const float4*)x)[i];
  __half2 h01 = __floats2half2_rn(v.x, v.y);
  __half2 h23 = __floats2half2_rn(v.z, v.w);
  ((__half2*)ah)[2 * i + 0] = h01;
  ((__half2*)ah)[2 * i + 1] = h23;
}

// ---------------------------------------------------------------------------
// Kernel 0b: W [K,N] -> W^T [N,K] fp16
// ---------------------------------------------------------------------------
__global__ void convert_w_kernel(const float* __restrict__ W,
                                 __half* __restrict__ wt) {
  int idx = blockIdx.x * blockDim.x + threadIdx.x;
  if (idx >= D_DIM * D_DIM) return;
  int k = idx / D_DIM;
  int n = idx - k * D_DIM;
  wt[(size_t)n * D_DIM + k] = __float2half_rn(W[idx]);
}

// ---------------------------------------------------------------------------
// Kernel 1: fp16 mma.sync GEMM (per group).  C = A @ Wt^T + bias
// CTA 128x128, 4 warps (64x64 tiles), BK=32, 4-stage cp.async, occupancy 2.
// SMEM rows padded to 80B -> conflict-free ldmatrix.
// ---------------------------------------------------------------------------
#define BK 32
#define NITER (D_DIM / BK)     // 24
#define ROWB 80
#define TILE_B (128 * ROWB)    // 10240
#define STAGE_BYTES (2 * TILE_B)
#define NSTAGES 4
#define GEMM_SMEM (NSTAGES * STAGE_BYTES)  // 81920

__global__ __launch_bounds__(128, 2) void gemm_mma_kernel(
    const __half* __restrict__ A, const __half* __restrict__ Bm,
    const float* __restrict__ bias, float* __restrict__ C) {
  extern __shared__ char smem[];
  const uint32_t sbase = smem_to_u32(smem);
  const int tid = threadIdx.x;
  const int wid = tid >> 5;
  const int lane = tid & 31;
  const int wm = wid >> 1;
  const int wn = wid & 1;
  const int brow = blockIdx.y * 128;
  const int bcol = blockIdx.x * 128;

  const int sub = lane >> 3;
  const int rown = lane & 7;
  const int lrow = (sub & 1) * 8 + rown;
  const int lchunk = (sub >> 1) * 16;

  float acc[4][8][4];
#pragma unroll
  for (int i = 0; i < 4; i++)
#pragma unroll
    for (int j = 0; j < 8; j++)
#pragma unroll
      for (int q = 0; q < 4; q++) acc[i][j][q] = 0.0f;

#define LOAD_STAGE(s, k0)                                                     \
  do {                                                                        \
    uint32_t abase_ = sbase + (s) * STAGE_BYTES;                              \
    uint32_t bbase_ = abase_ + TILE_B;                                        \
    _Pragma("unroll") for (int i_ = 0; i_ < 4; i_++) {                        \
      int lin_ = i_ * 128 + tid;                                              \
      int row_ = lin_ >> 2, c_ = lin_ & 3;                                    \
      cp16(abase_ + row_ * ROWB + c_ * 16,                                    \
           A + (size_t)(brow + row_) * D_DIM + (k0) + c_ * 8);                \
      cp16(bbase_ + row_ * ROWB + c_ * 16,                                    \
           Bm + (size_t)(bcol + row_) * D_DIM + (k0) + c_ * 8);               \
    }                                                                         \
    CP_COMMIT();                                                              \
  } while (0)

  LOAD_STAGE(0, 0);
  LOAD_STAGE(1, BK);
  LOAD_STAGE(2, 2 * BK);

  for (int it = 0; it < NITER; ++it) {
    CP_WAIT(2);
    __syncthreads();
    if (it + 3 < NITER) {
      LOAD_STAGE((it + 3) & 3, (it + 3) * BK);
    } else {
      CP_COMMIT();  // keep group count uniform
    }
    const uint32_t abase = sbase + (it & 3) * STAGE_BYTES;
    const uint32_t bbase = abase + TILE_B;
#pragma unroll
    for (int ks = 0; ks < 2; ks++) {
      uint32_t af[4][4], bf[4][4];
#pragma unroll
      for (int mt = 0; mt < 4; mt++)
        ldsm4(af[mt],
              abase + (wm * 64 + mt * 16 + lrow) * ROWB + lchunk + ks * 32);
#pragma unroll
      for (int nt = 0; nt < 4; nt++)
        ldsm4(bf[nt],
              bbase + (wn * 64 + nt * 16 + lrow) * ROWB + lchunk + ks * 32);
#pragma unroll
      for (int mt = 0; mt < 4; mt++)
#pragma unroll
        for (int nt = 0; nt < 4; nt++) {
          mma16816(acc[mt][2 * nt + 0], af[mt], bf[nt][0], bf[nt][2]);
          mma16816(acc[mt][2 * nt + 1], af[mt], bf[nt][1], bf[nt][3]);
        }
    }
  }

  const int gr = lane >> 2;
  const int gc2 = (lane & 3) * 2;
#pragma unroll
  for (int mt = 0; mt < 4; mt++) {
    const int r0 = brow + wm * 64 + mt * 16 + gr;
#pragma unroll
    for (int n8 = 0; n8 < 8; n8++) {
      const int col = bcol + wn * 64 + n8 * 8 + gc2;
      const float b0 = __ldg(&bias[col]);
      const float b1 = __ldg(&bias[col + 1]);
      float2 v0 = make_float2(acc[mt][n8][0] + b0, acc[mt][n8][1] + b1);
      float2 v1 = make_float2(acc[mt][n8][2] + b0, acc[mt][n8][3] + b1);
      *(float2*)&C[(size_t)r0 * D_DIM + col] = v0;
      *(float2*)&C[(size_t)(r0 + 8) * D_DIM + col] = v1;
    }
  }
}

// ---------------------------------------------------------------------------
// Kernel 2a/4a: per-chunk INCLUSIVE local scan + chunk sum (nb batches).
// ---------------------------------------------------------------------------
template <int SEQ, int CH>
__global__ void localscan_kernel(const float* __restrict__ x,
                                 float* __restrict__ lc,
                                 float* __restrict__ part, int nb) {
  constexpr int NCH = SEQ / CH;
  const int idx = blockIdx.x * blockDim.x + threadIdx.x;
  if (idx >= nb * NCH * D_DIM) return;
  const int d = idx % D_DIM;
  const int t = idx / D_DIM;
  const int c = t % NCH;
  const int b = t / NCH;
  const size_t base = ((size_t)b * SEQ + (size_t)c * CH) * D_DIM + d;
  const float* xp = x + base;
  float* lp = lc + base;
  float run = 0.0f;
  for (int r = 0; r < CH; r += 8) {
    float v[8];
#pragma unroll
    for (int u = 0; u < 8; u++) v[u] = xp[(size_t)(r + u) * D_DIM];
#pragma unroll
    for (int u = 0; u < 8; u++) {
      run += v[u];
      lp[(size_t)(r + u) * D_DIM] = run;
    }
  }
  part[idx] = run;
}

// ---------------------------------------------------------------------------
// Kernel 2b/4b: in-place exclusive scan of chunk sums.
// ---------------------------------------------------------------------------
template <int NCH>
__global__ void chunkpref_kernel(float* __restrict__ part, int nb) {
  const int idx = blockIdx.x * blockDim.x + threadIdx.x;
  if (idx >= nb * D_DIM) return;
  const int b = idx / D_DIM;
  const int d = idx - b * D_DIM;
  float* pp = part + (size_t)b * NCH * D_DIM + d;
  float run = 0.0f;
#pragma unroll
  for (int c = 0; c < NCH; c++) {
    float v = pp[(size_t)c * D_DIM];
    pp[(size_t)c * D_DIM] = run;
    run += v;
  }
}

// ---------------------------------------------------------------------------
// Kernel 3/5: segment mean from local scans + chunk prefixes.
// csum(g) = g==0 ? 0 : pref[(g-1)/CH] + lc[g-1]
// ---------------------------------------------------------------------------
template <int NSEG, int SEQ, int CH>
__global__ void seg_mean_kernel(const float* __restrict__ lc,
                                const float* __restrict__ pref,
                                const int* __restrict__ bounds,
                                float* __restrict__ out, int nb) {
  constexpr int NCH = SEQ / CH;
  const int idx = blockIdx.x * blockDim.x + threadIdx.x;
  if (idx >= nb * NSEG * D_DIM) return;
  const int d = idx % D_DIM;
  const int t = idx / D_DIM;
  const int seg = t % NSEG;
  const int b = t / NSEG;
  const int s0 = bounds[(b * NSEG + seg) * 2 + 0];
  const int s1 = bounds[(b * NSEG + seg) * 2 + 1];
  const int len = s1 - s0;
  float r = 0.0f;
  if (len > 0) {
    const float* lcb = lc + (size_t)b * SEQ * D_DIM + d;
    const float* pfb = pref + (size_t)b * NCH * D_DIM + d;
    float v1, v0;
    {
      int gm = s1 - 1;
      v1 = pfb[(size_t)(gm / CH) * D_DIM] + lcb[(size_t)gm * D_DIM];
    }
    if (s0 == 0) {
      v0 = 0.0f;
    } else {
      int gm = s0 - 1;
      v0 = pfb[(size_t)(gm / CH) * D_DIM] + lcb[(size_t)gm * D_DIM];
    }
    r = (v1 - v0) / (float)len;
  }
  out[idx] = r;
}

// ---------------------------------------------------------------------------
// Kernel 6: file mean
// ---------------------------------------------------------------------------
__global__ void file_mean_kernel(const float* __restrict__ func,
                                 float* __restrict__ file, int nb) {
  const int idx = blockIdx.x * blockDim.x + threadIdx.x;
  if (idx >= nb * D_DIM) return;
  const int b = idx / D_DIM;
  const int d = idx - b * D_DIM;
  const float* fp = func + (size_t)b * NF_DIM * D_DIM + d;
  float s = 0.0f;
#pragma unroll
  for (int f = 0; f < NF_DIM; f++) s += fp[(size_t)f * D_DIM];
  file[idx] = s * (1.0f / NF_DIM);
}

// ---------------------------------------------------------------------------
// Launch: 4 batch-groups pipelined across 3 streams.
//   stream0: conv_a(g0) -> gemm(g0..g3)            (tensor pipe saturated)
//   sConv:   conv_a(g1..g3)                         (under gemm(g0))
//   sTail:   tail(g) after gemm(g)                  (DRAM work under later gemms)
// ---------------------------------------------------------------------------
extern "C" void kernel_launch(void* const* d_in, const int* in_sizes, int n_in,
                              void* d_out, int out_size) {
  const float* hidden = (const float*)d_in[0];  // [B, S, D]
  const float* W      = (const float*)d_in[1];  // [D, D]
  const float* bias   = (const float*)d_in[2];  // [D]
  const int*   lb     = (const int*)d_in[3];    // [B, NL, 2]
  const int*   fb     = (const int*)d_in[4];    // [B, NF, 2]

  float* out   = (float*)d_out;
  float* token = out;                                    // [B, S, D]
  float* line  = token + (size_t)B_DIM * S_DIM * D_DIM;  // [B, NL, D]
  float* func  = line + (size_t)B_DIM * NL_DIM * D_DIM;  // [B, NF, D]
  float* file  = func + (size_t)B_DIM * NF_DIM * D_DIM;  // [B, D]

  float *lc_tok, *lc_line, *pref_tok, *pref_line;
  __half *ah, *wt;
  cudaGetSymbolAddress((void**)&lc_tok, g_lc_tok);
  cudaGetSymbolAddress((void**)&lc_line, g_lc_line);
  cudaGetSymbolAddress((void**)&pref_tok, g_pref_tok);
  cudaGetSymbolAddress((void**)&pref_line, g_pref_line);
  cudaGetSymbolAddress((void**)&ah, g_Ah);
  cudaGetSymbolAddress((void**)&wt, g_Wt);

  cudaFuncSetAttribute(gemm_mma_kernel,
                       cudaFuncAttributeMaxDynamicSharedMemorySize, GEMM_SMEM);

  // One-time host resources (created on the uncaptured correctness call;
  // only record/wait during capture — no device allocation involved).
  static cudaStream_t sConv = nullptr, sTail = nullptr;
  static cudaEvent_t evRoot, evConv[NGROUPS], evGemm[NGROUPS], evTail;
  if (sConv == nullptr) {
    cudaStreamCreateWithFlags(&sConv, cudaStreamNonBlocking);
    cudaStreamCreateWithFlags(&sTail, cudaStreamNonBlocking);
    cudaEventCreateWithFlags(&evRoot, cudaEventDisableTiming);
    cudaEventCreateWithFlags(&evTail, cudaEventDisableTiming);
    for (int g = 0; g < NGROUPS; g++) {
      cudaEventCreateWithFlags(&evConv[g], cudaEventDisableTiming);
      cudaEventCreateWithFlags(&evGemm[g], cudaEventDisableTiming);
    }
  }

  // Per-group sizes/offsets
  const size_t TOKG = (size_t)GRP * S_DIM * D_DIM;   // token/lc elems per group
  const size_t PRSG = (size_t)GRP * NCH_S * D_DIM;
  const size_t LING = (size_t)GRP * NL_DIM * D_DIM;
  const size_t PRLG = (size_t)GRP * NCH_L * D_DIM;
  const size_t FUNG = (size_t)GRP * NF_DIM * D_DIM;
  const size_t FILG = (size_t)GRP * D_DIM;
  const int n4g = (int)(TOKG / 4);

  // Fork side streams off the capture-origin stream.
  cudaEventRecord(evRoot, 0);
  cudaStreamWaitEvent(sConv, evRoot, 0);
  cudaStreamWaitEvent(sTail, evRoot, 0);

  // Weight conversion + group-0 A conversion on main stream.
  {
    int nw = D_DIM * D_DIM;
    convert_w_kernel<<<(nw + 255) / 256, 256, 0, 0>>>(W, wt);
    convert_a_kernel<<<(n4g + 255) / 256, 256, 0, 0>>>(hidden, ah, n4g);
  }
  // Groups 1..3 A conversion on sConv.
  for (int g = 1; g < NGROUPS; g++) {
    convert_a_kernel<<<(n4g + 255) / 256, 256, 0, sConv>>>(
        hidden + (size_t)g * TOKG, ah + (size_t)g * TOKG, n4g);
    cudaEventRecord(evConv[g], sConv);
  }
  // GEMM train on main stream.
  for (int g = 0; g < NGROUPS; g++) {
    if (g > 0) cudaStreamWaitEvent(0, evConv[g], 0);
    dim3 grid(D_DIM / 128, (GRP * S_DIM) / 128);  // (6, 128)
    gemm_mma_kernel<<<grid, 128, GEMM_SMEM, 0>>>(
        ah + (size_t)g * TOKG, wt, bias, token + (size_t)g * TOKG);
    cudaEventRecord(evGemm[g], 0);
  }
  // Per-group tail on sTail.
  for (int g = 0; g < NGROUPS; g++) {
    cudaStreamWaitEvent(sTail, evGemm[g], 0);
    const float* tok_g = token + (size_t)g * TOKG;
    float* lc_g = lc_tok + (size_t)g * TOKG;
    float* prs_g = pref_tok + (size_t)g * PRSG;
    float* line_g = line + (size_t)g * LING;
    float* lcl_g = lc_line + (size_t)g * LING;
    float* prl_g = pref_line + (size_t)g * PRLG;
    float* func_g = func + (size_t)g * FUNG;
    float* file_g = file + (size_t)g * FILG;
    const int* lb_g = lb + (size_t)g * GRP * NL_DIM * 2;
    const int* fb_g = fb + (size_t)g * GRP * NF_DIM * 2;
    {
      int n = GRP * NCH_S * D_DIM;
      localscan_kernel<S_DIM, CH_S><<<(n + 255) / 256, 256, 0, sTail>>>(
          tok_g, lc_g, prs_g, GRP);
      int m = GRP * D_DIM;
      chunkpref_kernel<NCH_S><<<(m + 255) / 256, 256, 0, sTail>>>(prs_g, GRP);
    }
    {
      int n = GRP * NL_DIM * D_DIM;
      seg_mean_kernel<NL_DIM, S_DIM, CH_S><<<(n + 255) / 256, 256, 0, sTail>>>(
          lc_g, prs_g, lb_g, line_g, GRP);
    }
    {
      int n = GRP * NCH_L * D_DIM;
      localscan_kernel<NL_DIM, CH_L><<<(n + 255) / 256, 256, 0, sTail>>>(
          line_g, lcl_g, prl_g, GRP);
      int m = GRP * D_DIM;
      chunkpref_kernel<NCH_L><<<(m + 255) / 256, 256, 0, sTail>>>(prl_g, GRP);
    }
    {
      int n = GRP * NF_DIM * D_DIM;
      seg_mean_kernel<NF_DIM, NL_DIM, CH_L><<<(n + 255) / 256, 256, 0, sTail>>>(
          lcl_g, prl_g, fb_g, func_g, GRP);
    }
    {
      int n = GRP * D_DIM;
      file_mean_kernel<<<(n + 255) / 256, 256, 0, sTail>>>(func_g, file_g, GRP);
    }
  }
  // Join.
  cudaEventRecord(evTail, sTail);
  cudaStreamWaitEvent(0, evTail, 0);
}

// round 15
// speedup vs baseline: 1.1107x; 1.1107x over previous
#include <cuda_runtime.h>
#include <cuda_fp16.h>
#include <cstdint>

// Problem constants
#define B_DIM  32
#define S_DIM  2048
#define D_DIM  768
#define NL_DIM 512
#define NF_DIM 64

#define MTOT (B_DIM * S_DIM)      // 65536

// Chunked-scan geometry
#define CH_S 128                  // == GEMM tile M -> scan fused into epilogue
#define NCH_S (S_DIM / CH_S)      // 16
#define CH_L 64
#define NCH_L (NL_DIM / CH_L)     // 8

// ---------------------------------------------------------------------------
// Scratch (__device__ globals; allocation-free rule)
// ---------------------------------------------------------------------------
__device__ float g_lc_tok[(size_t)B_DIM * S_DIM * D_DIM];    // ~201 MB local scans
__device__ float g_lc_line[(size_t)B_DIM * NL_DIM * D_DIM];  // ~50 MB
__device__ float g_pref_tok[(size_t)B_DIM * NCH_S * D_DIM];  // chunk sums->prefixes
__device__ float g_pref_line[(size_t)B_DIM * NCH_L * D_DIM];
__device__ __align__(128) __half g_Ah[(size_t)MTOT * D_DIM];   // ~100 MB fp16
__device__ __align__(128) __half g_Wt[(size_t)D_DIM * D_DIM];  // W^T fp16

// ---------------------------------------------------------------------------
// PTX helpers (sm_80-portable: cp.async, ldmatrix, mma.sync f16)
// ---------------------------------------------------------------------------
__device__ __forceinline__ uint32_t smem_to_u32(const void* p) {
  uint32_t a;
  asm("{ .reg .u64 t; cvta.to.shared.u64 t, %1; cvt.u32.u64 %0, t; }"
      : "=r"(a) : "l"(p));
  return a;
}

__device__ __forceinline__ void cp16(uint32_t dst, const void* src) {
  asm volatile("cp.async.cg.shared.global [%0], [%1], 16;\n" ::"r"(dst),
               "l"(src));
}
#define CP_COMMIT() asm volatile("cp.async.commit_group;\n" ::: "memory")
#define CP_WAIT(n) asm volatile("cp.async.wait_group %0;\n" ::"n"(n) : "memory")

__device__ __forceinline__ void ldsm4(uint32_t* r, uint32_t addr) {
  asm volatile(
      "ldmatrix.sync.aligned.m8n8.x4.shared.b16 {%0,%1,%2,%3}, [%4];"
      : "=r"(r[0]), "=r"(r[1]), "=r"(r[2]), "=r"(r[3])
      : "r"(addr));
}

__device__ __forceinline__ void mma16816(float* c, const uint32_t* a,
                                         uint32_t b0, uint32_t b1) {
  asm volatile(
      "mma.sync.aligned.m16n8k16.row.col.f32.f16.f16.f32 "
      "{%0,%1,%2,%3}, {%4,%5,%6,%7}, {%8,%9}, {%0,%1,%2,%3};"
      : "+f"(c[0]), "+f"(c[1]), "+f"(c[2]), "+f"(c[3])
      : "r"(a[0]), "r"(a[1]), "r"(a[2]), "r"(a[3]), "r"(b0), "r"(b1));
}

// ---------------------------------------------------------------------------
// Kernel 0a: fp32 -> fp16 (A)
// ---------------------------------------------------------------------------
__global__ void convert_a_kernel(const float* __restrict__ x,
                                 __half* __restrict__ ah, int n4) {
  int i = blockIdx.x * blockDim.x + threadIdx.x;
  if (i >= n4) return;
  float4 v = ((const float4*)x)[i];
  __half2 h01 = __floats2half2_rn(v.x, v.y);
  __half2 h23 = __floats2half2_rn(v.z, v.w);
  ((__half2*)ah)[2 * i + 0] = h01;
  ((__half2*)ah)[2 * i + 1] = h23;
}

// ---------------------------------------------------------------------------
// Kernel 0b: W [K,N] -> W^T [N,K] fp16
// ---------------------------------------------------------------------------
__global__ void convert_w_kernel(const float* __restrict__ W,
                                 __half* __restrict__ wt) {
  int idx = blockIdx.x * blockDim.x + threadIdx.x;
  if (idx >= D_DIM * D_DIM) return;
  int k = idx / D_DIM;
  int n = idx - k * D_DIM;
  wt[(size_t)n * D_DIM + k] = __float2half_rn(W[idx]);
}

// ---------------------------------------------------------------------------
// Kernel 1: fp16 mma.sync GEMM with FUSED chunk-local scan epilogue.
//   token[r][c] = (A@Wt^T)[r][c] + bias[c]
//   lc[r][c]    = inclusive scan of token over the CTA's 128 rows (one chunk)
//   part[b][ch][c] = chunk total
// CTA 128x128, 4 warps (64x64 tiles), BK=32, 4-stage cp.async, occupancy 2.
// SMEM rows padded to 80B -> conflict-free ldmatrix.
// ---------------------------------------------------------------------------
#define BK 32
#define NITER (D_DIM / BK)     // 24
#define ROWB 80
#define TILE_B (128 * ROWB)    // 10240
#define STAGE_BYTES (2 * TILE_B)
#define NSTAGES 4
#define GEMM_SMEM (NSTAGES * STAGE_BYTES)  // 81920
#define SP 132                 // staging row stride (floats), 128 + 4 pad

__global__ __launch_bounds__(128, 2) void gemm_mma_scan_kernel(
    const __half* __restrict__ A, const __half* __restrict__ Bm,
    const float* __restrict__ bias, float* __restrict__ C,
    float* __restrict__ lc, float* __restrict__ part) {
  extern __shared__ char smem[];
  const uint32_t sbase = smem_to_u32(smem);
  const int tid = threadIdx.x;
  const int wid = tid >> 5;
  const int lane = tid & 31;
  const int wm = wid >> 1;
  const int wn = wid & 1;
  const int brow = blockIdx.y * 128;
  const int bcol = blockIdx.x * 128;

  const int sub = lane >> 3;
  const int rown = lane & 7;
  const int lrow = (sub & 1) * 8 + rown;
  const int lchunk = (sub >> 1) * 16;

  float acc[4][8][4];
#pragma unroll
  for (int i = 0; i < 4; i++)
#pragma unroll
    for (int j = 0; j < 8; j++)
#pragma unroll
      for (int q = 0; q < 4; q++) acc[i][j][q] = 0.0f;

#define LOAD_STAGE(s, k0)                                                     \
  do {                                                                        \
    uint32_t abase_ = sbase + (s) * STAGE_BYTES;                              \
    uint32_t bbase_ = abase_ + TILE_B;                                        \
    _Pragma("unroll") for (int i_ = 0; i_ < 4; i_++) {                        \
      int lin_ = i_ * 128 + tid;                                              \
      int row_ = lin_ >> 2, c_ = lin_ & 3;                                    \
      cp16(abase_ + row_ * ROWB + c_ * 16,                                    \
           A + (size_t)(brow + row_) * D_DIM + (k0) + c_ * 8);                \
      cp16(bbase_ + row_ * ROWB + c_ * 16,                                    \
           Bm + (size_t)(bcol + row_) * D_DIM + (k0) + c_ * 8);               \
    }                                                                         \
    CP_COMMIT();                                                              \
  } while (0)

  LOAD_STAGE(0, 0);
  LOAD_STAGE(1, BK);
  LOAD_STAGE(2, 2 * BK);

  for (int it = 0; it < NITER; ++it) {
    CP_WAIT(2);
    __syncthreads();
    if (it + 3 < NITER) {
      LOAD_STAGE((it + 3) & 3, (it + 3) * BK);
    } else {
      CP_COMMIT();  // keep group count uniform
    }
    const uint32_t abase = sbase + (it & 3) * STAGE_BYTES;
    const uint32_t bbase = abase + TILE_B;
#pragma unroll
    for (int ks = 0; ks < 2; ks++) {
      uint32_t af[4][4], bf[4][4];
#pragma unroll
      for (int mt = 0; mt < 4; mt++)
        ldsm4(af[mt],
              abase + (wm * 64 + mt * 16 + lrow) * ROWB + lchunk + ks * 32);
#pragma unroll
      for (int nt = 0; nt < 4; nt++)
        ldsm4(bf[nt],
              bbase + (wn * 64 + nt * 16 + lrow) * ROWB + lchunk + ks * 32);
#pragma unroll
      for (int mt = 0; mt < 4; mt++)
#pragma unroll
        for (int nt = 0; nt < 4; nt++) {
          mma16816(acc[mt][2 * nt + 0], af[mt], bf[nt][0], bf[nt][2]);
          mma16816(acc[mt][2 * nt + 1], af[mt], bf[nt][1], bf[nt][3]);
        }
    }
  }

  // --- Epilogue: token stores + SMEM tile staging ---
  CP_WAIT(0);
  __syncthreads();  // all smem pipeline reads done before restaging
  float* stg = (float*)smem;  // 128 x SP floats = 67,584 B <= 81,920 B
  const int gr = lane >> 2;
  const int gc2 = (lane & 3) * 2;
#pragma unroll
  for (int mt = 0; mt < 4; mt++) {
    const int r0l = wm * 64 + mt * 16 + gr;
    const int r0 = brow + r0l;
#pragma unroll
    for (int n8 = 0; n8 < 8; n8++) {
      const int coll = wn * 64 + n8 * 8 + gc2;
      const int col = bcol + coll;
      const float b0 = __ldg(&bias[col]);
      const float b1 = __ldg(&bias[col + 1]);
      float2 v0 = make_float2(acc[mt][n8][0] + b0, acc[mt][n8][1] + b1);
      float2 v1 = make_float2(acc[mt][n8][2] + b0, acc[mt][n8][3] + b1);
      *(float2*)&C[(size_t)r0 * D_DIM + col] = v0;
      *(float2*)&C[(size_t)(r0 + 8) * D_DIM + col] = v1;
      stg[r0l * SP + coll] = v0.x;
      stg[r0l * SP + coll + 1] = v0.y;
      stg[(r0l + 8) * SP + coll] = v1.x;
      stg[(r0l + 8) * SP + coll + 1] = v1.y;
    }
  }
  __syncthreads();
  // --- Fused chunk-local scan: thread = one of 128 columns ---
  {
    const int b = brow / S_DIM;
    const int ch = (brow % S_DIM) / CH_S;
    float* lcp = lc + (size_t)brow * D_DIM + bcol + tid;
    float run = 0.0f;
#pragma unroll 8
    for (int r = 0; r < 128; r++) {
      run += stg[r * SP + tid];
      lcp[(size_t)r * D_DIM] = run;
    }
    part[((size_t)(b * NCH_S + ch)) * D_DIM + bcol + tid] = run;
  }
}

// ---------------------------------------------------------------------------
// Kernel 2b/4b: in-place exclusive scan of chunk sums.
// ---------------------------------------------------------------------------
template <int NCH>
__global__ void chunkpref_kernel(float* __restrict__ part) {
  const int idx = blockIdx.x * blockDim.x + threadIdx.x;
  if (idx >= B_DIM * D_DIM) return;
  const int b = idx / D_DIM;
  const int d = idx - b * D_DIM;
  float* pp = part + (size_t)b * NCH * D_DIM + d;
  float run = 0.0f;
#pragma unroll
  for (int c = 0; c < NCH; c++) {
    float v = pp[(size_t)c * D_DIM];
    pp[(size_t)c * D_DIM] = run;
    run += v;
  }
}

// ---------------------------------------------------------------------------
// Kernel 3: FUSED line seg-mean + line-level chunk-local scan.
// thread = (b, line-chunk, d): 64 segments serial.
//   line[seg]    = segment mean from token-level scans
//   lc_line[seg] = inclusive scan within the 64-segment chunk
//   part_line    = chunk total
// ---------------------------------------------------------------------------
__global__ void seg_scan_line_kernel(const float* __restrict__ lc_tok,
                                     const float* __restrict__ pref_tok,
                                     const int* __restrict__ lb,
                                     float* __restrict__ line,
                                     float* __restrict__ lc_line,
                                     float* __restrict__ part_line) {
  const int idx = blockIdx.x * blockDim.x + threadIdx.x;
  if (idx >= B_DIM * NCH_L * D_DIM) return;
  const int d = idx % D_DIM;
  const int t = idx / D_DIM;
  const int cl = t % NCH_L;
  const int b = t / NCH_L;
  const float* lcb = lc_tok + (size_t)b * S_DIM * D_DIM + d;
  const float* pfb = pref_tok + (size_t)b * NCH_S * D_DIM + d;
  float run = 0.0f;
  for (int j = 0; j < CH_L; j++) {
    const int seg = cl * CH_L + j;
    const int s0 = lb[(b * NL_DIM + seg) * 2 + 0];
    const int s1 = lb[(b * NL_DIM + seg) * 2 + 1];
    const int len = s1 - s0;
    float r = 0.0f;
    if (len > 0) {
      int g1 = s1 - 1;
      float v1 = pfb[(size_t)(g1 / CH_S) * D_DIM] + lcb[(size_t)g1 * D_DIM];
      float v0 = 0.0f;
      if (s0 > 0) {
        int g0 = s0 - 1;
        v0 = pfb[(size_t)(g0 / CH_S) * D_DIM] + lcb[(size_t)g0 * D_DIM];
      }
      r = (v1 - v0) / (float)len;
    }
    const size_t o = (size_t)(b * NL_DIM + seg) * D_DIM + d;
    line[o] = r;
    run += r;
    lc_line[o] = run;
  }
  part_line[(size_t)(b * NCH_L + cl) * D_DIM + d] = run;
}

// ---------------------------------------------------------------------------
// Kernel 5: FUSED function seg-mean + file mean.  thread = (b, d).
// ---------------------------------------------------------------------------
__global__ void func_file_kernel(const float* __restrict__ lc_line,
                                 const float* __restrict__ pref_line,
                                 const int* __restrict__ fb,
                                 float* __restrict__ func,
                                 float* __restrict__ file) {
  const int idx = blockIdx.x * blockDim.x + threadIdx.x;
  if (idx >= B_DIM * D_DIM) return;
  const int b = idx / D_DIM;
  const int d = idx - b * D_DIM;
  const float* lcb = lc_line + (size_t)b * NL_DIM * D_DIM + d;
  const float* pfb = pref_line + (size_t)b * NCH_L * D_DIM + d;
  float s = 0.0f;
#pragma unroll 4
  for (int f = 0; f < NF_DIM; f++) {
    const int s0 = fb[(b * NF_DIM + f) * 2 + 0];
    const int s1 = fb[(b * NF_DIM + f) * 2 + 1];
    const int len = s1 - s0;
    float r = 0.0f;
    if (len > 0) {
      int g1 = s1 - 1;
      float v1 = pfb[(size_t)(g1 / CH_L) * D_DIM] + lcb[(size_t)g1 * D_DIM];
      float v0 = 0.0f;
      if (s0 > 0) {
        int g0 = s0 - 1;
        v0 = pfb[(size_t)(g0 / CH_L) * D_DIM] + lcb[(size_t)g0 * D_DIM];
      }
      r = (v1 - v0) / (float)len;
    }
    func[(size_t)(b * NF_DIM + f) * D_DIM + d] = r;
    s += r;
  }
  file[(size_t)b * D_DIM + d] = s * (1.0f / NF_DIM);
}

// ---------------------------------------------------------------------------
// Launch (single stream, 7 kernels)
// ---------------------------------------------------------------------------
extern "C" void kernel_launch(void* const* d_in, const int* in_sizes, int n_in,
                              void* d_out, int out_size) {
  const float* hidden = (const float*)d_in[0];  // [B, S, D]
  const float* W      = (const float*)d_in[1];  // [D, D]
  const float* bias   = (const float*)d_in[2];  // [D]
  const int*   lb     = (const int*)d_in[3];    // [B, NL, 2]
  const int*   fb     = (const int*)d_in[4];    // [B, NF, 2]

  float* out   = (float*)d_out;
  float* token = out;                                    // [B, S, D]
  float* line  = token + (size_t)B_DIM * S_DIM * D_DIM;  // [B, NL, D]
  float* func  = line + (size_t)B_DIM * NL_DIM * D_DIM;  // [B, NF, D]
  float* file  = func + (size_t)B_DIM * NF_DIM * D_DIM;  // [B, D]

  float *lc_tok, *lc_line, *pref_tok, *pref_line;
  __half *ah, *wt;
  cudaGetSymbolAddress((void**)&lc_tok, g_lc_tok);
  cudaGetSymbolAddress((void**)&lc_line, g_lc_line);
  cudaGetSymbolAddress((void**)&pref_tok, g_pref_tok);
  cudaGetSymbolAddress((void**)&pref_line, g_pref_line);
  cudaGetSymbolAddress((void**)&ah, g_Ah);
  cudaGetSymbolAddress((void**)&wt, g_Wt);

  cudaFuncSetAttribute(gemm_mma_scan_kernel,
                       cudaFuncAttributeMaxDynamicSharedMemorySize, GEMM_SMEM);

  // 0) fp16 conversions
  {
    int nw = D_DIM * D_DIM;
    convert_w_kernel<<<(nw + 255) / 256, 256>>>(W, wt);
    int n4 = (MTOT * D_DIM) / 4;
    convert_a_kernel<<<(n4 + 255) / 256, 256>>>(hidden, ah, n4);
  }
  // 1) token = hidden @ W + bias, fused with S-level chunk-local scan
  {
    dim3 grid(D_DIM / 128, MTOT / 128);  // (6, 512)
    gemm_mma_scan_kernel<<<grid, 128, GEMM_SMEM>>>(ah, wt, bias, token,
                                                   lc_tok, pref_tok);
  }
  // 2) chunk prefixes at S level
  {
    int m = B_DIM * D_DIM;
    chunkpref_kernel<NCH_S><<<(m + 255) / 256, 256>>>(pref_tok);
  }
  // 3) line segment means + NL-level chunk-local scan (fused)
  {
    int n = B_DIM * NCH_L * D_DIM;
    seg_scan_line_kernel<<<(n + 255) / 256, 256>>>(lc_tok, pref_tok, lb, line,
                                                   lc_line, pref_line);
  }
  // 4) chunk prefixes at NL level
  {
    int m = B_DIM * D_DIM;
    chunkpref_kernel<NCH_L><<<(m + 255) / 256, 256>>>(pref_line);
  }
  // 5) function segment means + file mean (fused)
  {
    int n = B_DIM * D_DIM;
    func_file_kernel<<<(n + 255) / 256, 256>>>(lc_line, pref_line, fb, func,
                                               file);
  }
}